// round 2
// baseline (speedup 1.0000x reference)
#include <cuda_runtime.h>

#define SEQ 8192
#define EMB 768
#define DIM 64
#define PAD 68

// Scratch for projected Q (pre-scaled by 1/sqrt(D)), K, V.
__device__ float g_Q[SEQ * DIM];
__device__ float g_K[SEQ * DIM];
__device__ float g_V[SEQ * DIM];

// ---------------------------------------------------------------------------
// Kernel 1: QKV projection. C[8192,64] = X[8192,768] @ W[768,64].
// grid (128, 3): blockIdx.y selects W_Q / W_K / W_V. 256 threads, 4x4 micro.
// ---------------------------------------------------------------------------
__global__ __launch_bounds__(256, 1) void qkv_kernel(
    const float* __restrict__ X,
    const float* __restrict__ WQ,
    const float* __restrict__ WK,
    const float* __restrict__ WV)
{
    __shared__ float Xs[64][17];     // [m][k], padded (scalar reads)
    __shared__ float Ws[16][PAD];    // [k][n], padded for float4

    const int tid = threadIdx.x;
    const int tx = tid & 15;
    const int ty = tid >> 4;
    const int mbase = blockIdx.x * 64;
    const int w = blockIdx.y;
    const float* __restrict__ W = (w == 0) ? WQ : ((w == 1) ? WK : WV);

    const int xr = tid >> 2;          // 0..63
    const int xc = (tid & 3) << 2;    // 0,4,8,12
    const int wr = tid >> 4;          // 0..15
    const int wc = (tid & 15) << 2;   // 0..60

    float acc[4][4];
#pragma unroll
    for (int i = 0; i < 4; i++)
#pragma unroll
        for (int j = 0; j < 4; j++) acc[i][j] = 0.f;

    for (int kb = 0; kb < EMB; kb += 16) {
        float4 xv = *(const float4*)(X + (mbase + xr) * EMB + kb + xc);
        Xs[xr][xc + 0] = xv.x;
        Xs[xr][xc + 1] = xv.y;
        Xs[xr][xc + 2] = xv.z;
        Xs[xr][xc + 3] = xv.w;
        *(float4*)&Ws[wr][wc] = *(const float4*)(W + (kb + wr) * DIM + wc);
        __syncthreads();
#pragma unroll
        for (int k = 0; k < 16; k++) {
            float a[4];
#pragma unroll
            for (int i = 0; i < 4; i++) a[i] = Xs[4 * ty + i][k];
            float4 b4 = *(const float4*)&Ws[k][4 * tx];
            const float* b = (const float*)&b4;
#pragma unroll
            for (int i = 0; i < 4; i++)
#pragma unroll
                for (int j = 0; j < 4; j++) acc[i][j] += a[i] * b[j];
        }
        __syncthreads();
    }

    // Pre-fold the 1/sqrt(D) = 1/8 softmax scale into Q.
    const float scale = (w == 0) ? 0.125f : 1.0f;
    float* dst = (w == 0) ? g_Q : ((w == 1) ? g_K : g_V);
#pragma unroll
    for (int i = 0; i < 4; i++) {
        float4 o4;
        o4.x = acc[i][0] * scale;
        o4.y = acc[i][1] * scale;
        o4.z = acc[i][2] * scale;
        o4.w = acc[i][3] * scale;
        *(float4*)(dst + (mbase + 4 * ty + i) * DIM + 4 * tx) = o4;
    }
}

// ---------------------------------------------------------------------------
// Kernel 2: flash attention, fp32, online softmax.
// grid 128 (BM=64 query rows per block), 256 threads (16x16 layout).
// Thread (ty,tx) owns S/O rows {4*ty+i} and columns {tx + 16*j}.
// Column mapping tx+16j (not 4tx+j) keeps K-row float4 smem loads at
// 2-way instead of 8-way bank conflicts.
// ---------------------------------------------------------------------------
extern __shared__ float smf[];

__global__ __launch_bounds__(256, 1) void attn_kernel(float* __restrict__ out)
{
    float* Qs = smf;                  // [64][PAD]
    float* Ks = smf + 64 * PAD;       // [64][PAD]
    float* Vs = smf + 2 * 64 * PAD;   // [64][PAD]
    float* Ps = smf + 3 * 64 * PAD;   // [64][PAD]

    const int tid = threadIdx.x;
    const int tx = tid & 15;
    const int ty = tid >> 4;
    const int qbase = blockIdx.x * 64;
    const int lr = tid >> 2;          // load row 0..63
    const int lc = (tid & 3) << 4;    // load col 0,16,32,48

#pragma unroll
    for (int u = 0; u < 4; u++)
        *(float4*)&Qs[lr * PAD + lc + 4 * u] =
            *(const float4*)(g_Q + (qbase + lr) * DIM + lc + 4 * u);

    float m[4], l[4], o[4][4];
#pragma unroll
    for (int i = 0; i < 4; i++) {
        m[i] = -1e30f;
        l[i] = 0.f;
#pragma unroll
        for (int j = 0; j < 4; j++) o[i][j] = 0.f;
    }

    for (int nb = 0; nb < SEQ; nb += 64) {
        // --- load K,V tile (64x64 each) ---
#pragma unroll
        for (int u = 0; u < 4; u++) {
            *(float4*)&Ks[lr * PAD + lc + 4 * u] =
                *(const float4*)(g_K + (nb + lr) * DIM + lc + 4 * u);
            *(float4*)&Vs[lr * PAD + lc + 4 * u] =
                *(const float4*)(g_V + (nb + lr) * DIM + lc + 4 * u);
        }
        __syncthreads();

        // --- S = Qs @ Ks^T (Q pre-scaled) ---
        float s[4][4];
#pragma unroll
        for (int i = 0; i < 4; i++)
#pragma unroll
            for (int j = 0; j < 4; j++) s[i][j] = 0.f;

#pragma unroll 4
        for (int d4 = 0; d4 < DIM; d4 += 4) {
            float4 a4[4], b4[4];
#pragma unroll
            for (int i = 0; i < 4; i++)
                a4[i] = *(const float4*)&Qs[(4 * ty + i) * PAD + d4];
#pragma unroll
            for (int j = 0; j < 4; j++)
                b4[j] = *(const float4*)&Ks[(tx + 16 * j) * PAD + d4];
#pragma unroll
            for (int i = 0; i < 4; i++) {
                const float* a = (const float*)&a4[i];
#pragma unroll
                for (int j = 0; j < 4; j++) {
                    const float* b = (const float*)&b4[j];
                    s[i][j] += a[0] * b[0];
                    s[i][j] += a[1] * b[1];
                    s[i][j] += a[2] * b[2];
                    s[i][j] += a[3] * b[3];
                }
            }
        }

        // --- online softmax; rows owned by 16 tx-lanes -> shfl reduce ---
#pragma unroll
        for (int i = 0; i < 4; i++) {
            float tm = fmaxf(fmaxf(s[i][0], s[i][1]), fmaxf(s[i][2], s[i][3]));
            tm = fmaxf(tm, __shfl_xor_sync(0xffffffffu, tm, 1));
            tm = fmaxf(tm, __shfl_xor_sync(0xffffffffu, tm, 2));
            tm = fmaxf(tm, __shfl_xor_sync(0xffffffffu, tm, 4));
            tm = fmaxf(tm, __shfl_xor_sync(0xffffffffu, tm, 8));
            float mnew = fmaxf(m[i], tm);
            float corr = __expf(m[i] - mnew);
            float rs = 0.f;
#pragma unroll
            for (int j = 0; j < 4; j++) {
                s[i][j] = __expf(s[i][j] - mnew);
                rs += s[i][j];
            }
            rs += __shfl_xor_sync(0xffffffffu, rs, 1);
            rs += __shfl_xor_sync(0xffffffffu, rs, 2);
            rs += __shfl_xor_sync(0xffffffffu, rs, 4);
            rs += __shfl_xor_sync(0xffffffffu, rs, 8);
            l[i] = l[i] * corr + rs;
            m[i] = mnew;
#pragma unroll
            for (int j = 0; j < 4; j++) {
                o[i][j] *= corr;
                Ps[(4 * ty + i) * PAD + tx + 16 * j] = s[i][j];
            }
        }
        __syncthreads();

        // --- O += P @ V ---
#pragma unroll 4
        for (int n4 = 0; n4 < 64; n4 += 4) {
            float4 p4[4];
#pragma unroll
            for (int i = 0; i < 4; i++)
                p4[i] = *(const float4*)&Ps[(4 * ty + i) * PAD + n4];
#pragma unroll
            for (int q = 0; q < 4; q++) {
                float v[4];
#pragma unroll
                for (int j = 0; j < 4; j++)
                    v[j] = Vs[(n4 + q) * PAD + tx + 16 * j];
#pragma unroll
                for (int i = 0; i < 4; i++) {
                    const float* p = (const float*)&p4[i];
#pragma unroll
                    for (int j = 0; j < 4; j++)
                        o[i][j] += p[q] * v[j];
                }
            }
        }
        __syncthreads();
    }

    // --- normalize + store ---
#pragma unroll
    for (int i = 0; i < 4; i++) {
        float inv = 1.0f / l[i];
#pragma unroll
        for (int j = 0; j < 4; j++)
            out[(qbase + 4 * ty + i) * DIM + tx + 16 * j] = o[i][j] * inv;
    }
}

// ---------------------------------------------------------------------------
extern "C" void kernel_launch(void* const* d_in, const int* in_sizes, int n_in,
                              void* d_out, int out_size)
{
    const float* X  = (const float*)d_in[0];
    const float* WQ = (const float*)d_in[1];
    const float* WK = (const float*)d_in[2];
    const float* WV = (const float*)d_in[3];
    float* out = (float*)d_out;

    const int smem_bytes = 4 * 64 * PAD * sizeof(float);  // 69632
    cudaFuncSetAttribute(attn_kernel,
                         cudaFuncAttributeMaxDynamicSharedMemorySize,
                         smem_bytes);

    dim3 g1(SEQ / 64, 3);
    qkv_kernel<<<g1, 256>>>(X, WQ, WK, WV);
    attn_kernel<<<SEQ / 64, 256, smem_bytes>>>(out);
}